// round 14
// baseline (speedup 1.0000x reference)
#include <cuda_runtime.h>
#include <math.h>

#define DEG2RAD 0.017453292519943295f
#define RAD2DEG 57.29577951308232f
#define TINY    1e-6f

// Expected DH table (all entries exactly-representable in fp32)
__constant__ float c_E[24] = {0.f,180.f,-650.f,0.f,  270.f,90.f,0.f,0.f,
                              800.f,0.f,0.f,0.f,     140.f,90.f,-908.f,0.f,
                              0.f,-96.f,0.f,0.f,     0.f,-65.f,260.f,0.f};

__device__ __forceinline__ void fsincos(float ang, float& s, float& c) {
    s = __sinf(ang);
    c = __cosf(ang);
}

__device__ __forceinline__ float sqrt_approx(float x) {
    float r;
    asm("sqrt.approx.f32 %0, %1;" : "=f"(r) : "f"(x));
    return r;
}

// Fast atan2 returning DEGREES directly: minimax coefficients pre-scaled by
// 180/pi, quadrant constants are 90/180. Max abs err ~6e-4 deg.
__device__ __forceinline__ float fast_atan2_deg(float y, float x) {
    float ax = fabsf(x), ay = fabsf(y);
    float mx = fmaxf(ax, ay), mn = fminf(ax, ay);
    float t  = __fdividef(mn, mx);
    float t2 = t * t;
    float p;
    p = fmaf(t2, -0.671580f, 3.016813f);
    p = fmaf(t2, p, -6.670985f);
    p = fmaf(t2, p,  11.089168f);
    p = fmaf(t2, p, -19.059124f);
    p = fmaf(t2, p,  57.294476f);
    float r = p * t;
    if (ay > ax)  r = 90.0f - r;
    if (x < 0.0f) r = 180.0f - r;
    return copysignf(r, y);
}

// x guaranteed >= 0: skips the x<0 quadrant fixup
__device__ __forceinline__ float fast_atan2_deg_posx(float y, float x) {
    float ay = fabsf(y);
    float mx = fmaxf(x, ay), mn = fminf(x, ay);
    float t  = __fdividef(mn, mx);
    float t2 = t * t;
    float p;
    p = fmaf(t2, -0.671580f, 3.016813f);
    p = fmaf(t2, p, -6.670985f);
    p = fmaf(t2, p,  11.089168f);
    p = fmaf(t2, p, -19.059124f);
    p = fmaf(t2, p,  57.294476f);
    float r = p * t;
    if (ay > x) r = 90.0f - r;
    return copysignf(r, y);
}

// Specialized FK for the known DH table (dead T20 trimmed, lazy row-1 joint 5).
__device__ __forceinline__ void fk_spec(float2 v0, float2 v1, float2 v2, float o[6]) {
    float a0 = v0.x * DEG2RAD, a1 = v0.y * DEG2RAD;
    float a2 = v1.x * DEG2RAD, a3 = v1.y * DEG2RAD;
    float a4 = v2.x * DEG2RAD, a5 = v2.y * DEG2RAD;

    float s0, c0, s1, c1, s12, c12, s3, c3, s4, c4, s5, c5;
    fsincos(a0, s0, c0);
    fsincos(a1, s1, c1);
    fsincos(a1 + a2, s12, c12);
    fsincos(a3, s3, c3);
    fsincos(a4, s4, c4);
    fsincos(a5, s5, c5);

    // Closed form of T = T0*T1*T2*T3 (alphas 180,90,0,90; offsets 0):
    float P = fmaf(140.f, c12, fmaf(-908.f, s12, fmaf(800.f, c1, 270.f)));
    float Q = fmaf(-800.f, s1, fmaf(-140.f, s12, fmaf(-908.f, c12, 650.f)));
    float c0c12 = c0 * c12, s0c12 = s0 * c12;

    float T00 = fmaf(c3, c0c12, s3 * s0);
    float T01 = fmaf(-s3, c0c12, c3 * s0);
    float T02 = c0 * s12;
    float T03 = c0 * P;
    float T10 = fmaf(-c3, s0c12, s3 * c0);
    float T11 = fmaf(s3, s0c12, c3 * c0);
    float T12 = -s0 * s12;
    float T13 = -s0 * P;
    float T20 = -c3 * s12;
    float T21 = s3 * s12;
    float T22 = c12;
    float T23 = Q;

    // Joint 4: alpha=-96deg, a=0, d=0 (translation unchanged)
    const float ca4 = -0.10452846326765347f, sa4 = -0.9945218953682733f;
    {
        float u, v, n0, n1;
        u = fmaf(ca4, T01, sa4 * T02); v = fmaf(ca4, T02, -sa4 * T01);
        n0 = fmaf(c4, T00, s4 * u); n1 = fmaf(-s4, T00, c4 * u);
        T00 = n0; T01 = n1; T02 = v;
        u = fmaf(ca4, T11, sa4 * T12); v = fmaf(ca4, T12, -sa4 * T11);
        n0 = fmaf(c4, T10, s4 * u); n1 = fmaf(-s4, T10, c4 * u);
        T10 = n0; T11 = n1; T12 = v;
        // row 2: T20 after this joint is never consumed downstream
        u = fmaf(ca4, T21, sa4 * T22); v = fmaf(ca4, T22, -sa4 * T21);
        n1 = fmaf(-s4, T20, c4 * u);
        T21 = n1; T22 = v;
    }

    // Joint 5: alpha=-65deg, a=0, d=260
    const float ca5 = 0.42261826174069944f, sa5 = -0.9063077870366499f;
    float T00f, T01f, T02f, T12f, T22f;
    {
        float u = fmaf(ca5, T01, sa5 * T02);
        T02f = fmaf(ca5, T02, -sa5 * T01);
        T00f = fmaf(c5, T00, s5 * u);
        T01f = fmaf(-s5, T00, c5 * u);
        T03  = fmaf(260.f, T02f, T03);
        // row 1: final T10/T11 only needed in the rare gimbal branch
        T12f = fmaf(ca5, T12, -sa5 * T11);
        T13  = fmaf(260.f, T12f, T13);
        // row 2: only T22, T23 needed downstream
        T22f = fmaf(ca5, T22, -sa5 * T21);
        T23  = fmaf(260.f, T22f, T23);
    }

    // Euler extraction (common path; identity cosA*T00 - sinA*T01 = sqrt(r2))
    float r2 = fmaf(T00f, T00f, T01f * T01f);
    float A  = fast_atan2_deg(-T01f, T00f);
    float Bd = fast_atan2_deg_posx(T02f, sqrt_approx(r2));
    float C  = fast_atan2_deg(-T12f, T22f);

    bool cond = (fabsf(T12f) <= TINY) && (fabsf(T22f) <= TINY);
    if (cond) {   // rare gimbal branch: lazily finish row 1 of joint 5
        float u1   = fmaf(ca5, T11, sa5 * T12);
        float T10f = fmaf(c5, T10, s5 * u1);
        float T11f = fmaf(-s5, T10, c5 * u1);
        A  = fast_atan2_deg(T10f, T11f);
        Bd = fast_atan2_deg(T02f, T22f);
        C  = 0.f;
    }

    o[0] = T03; o[1] = T13; o[2] = T23; o[3] = A; o[4] = Bd; o[5] = C;
}

// Generic fallback using runtime DH parameters (shared mem). Cold path.
__device__ void fk_generic(float2 v0, float2 v1, float2 v2, float o[6],
                           const float* ca_, const float* sa_,
                           const float* a_, const float* d_,
                           const float* off_) {
    float th[6] = {v0.x, v0.y, v1.x, v1.y, v2.x, v2.y};
    float T[3][4];
    {
        float s, c;
        fsincos(fmaf(th[0], DEG2RAD, off_[0]), s, c);
        float ca = ca_[0], sa = sa_[0], a = a_[0], d = d_[0];
        T[0][0] = c;      T[0][1] = -s;     T[0][2] = 0.f;  T[0][3] = a;
        T[1][0] = s * ca; T[1][1] = c * ca; T[1][2] = -sa;  T[1][3] = -sa * d;
        T[2][0] = s * sa; T[2][1] = c * sa; T[2][2] = ca;   T[2][3] = ca * d;
    }
    #pragma unroll
    for (int j = 1; j < 6; j++) {
        float s, c;
        fsincos(fmaf(th[j], DEG2RAD, off_[j]), s, c);
        float ca = ca_[j], sa = sa_[j], a = a_[j], d = d_[j];
        #pragma unroll
        for (int r = 0; r < 3; r++) {
            float t0 = T[r][0], t1 = T[r][1], t2 = T[r][2], t3 = T[r][3];
            float u = fmaf(ca, t1, sa * t2);
            float v = fmaf(ca, t2, -sa * t1);
            if (!(j == 5 && r == 2)) {
                T[r][0] = fmaf(c, t0,  s * u);
                T[r][1] = fmaf(-s, t0, c * u);
            }
            T[r][2] = v;
            T[r][3] = fmaf(a, t0, fmaf(d, v, t3));
        }
    }
    float T00 = T[0][0], T01 = T[0][1], T02 = T[0][2];
    float T10 = T[1][0], T11 = T[1][1], T12 = T[1][2];
    float T22 = T[2][2];

    float r2 = fmaf(T00, T00, T01 * T01);
    float A  = fast_atan2_deg(-T01, T00);
    float Bd = fast_atan2_deg_posx(T02, sqrt_approx(r2));
    float C  = fast_atan2_deg(-T12, T22);

    bool cond = (fabsf(T12) <= TINY) && (fabsf(T22) <= TINY);
    if (cond) {
        A  = fast_atan2_deg(T10, T11);
        Bd = fast_atan2_deg(T02, T22);
        C  = 0.f;
    }
    o[0] = T[0][3]; o[1] = T[1][3]; o[2] = T[2][3]; o[3] = A; o[4] = Bd; o[5] = C;
}

// Single persistent kernel. Warp-level DH check (no barrier, no extra launch);
// grid-stride loop with software prefetch; pointer-increment addressing
// (base + immediate-offset loads — keeps ptxas's batched LDG issue).
__global__ __launch_bounds__(256)
void fk_kernel(const float* __restrict__ theta,
               const float* __restrict__ dh,
               float* __restrict__ out, int B) {
    __shared__ float s_a[6], s_d[6], s_ca[6], s_sa[6], s_off[6];

    // Warp-uniform DH check: lanes 0-23 compare one element each (one
    // coalesced LDG, L1-hot after the first warp), then ballot.
    int lane = threadIdx.x & 31;
    bool okl = (lane < 24) ? (dh[lane] == c_E[lane]) : true;
    const bool spec = __all_sync(0xffffffffu, okl);

    int stride = gridDim.x * blockDim.x;
    int i = blockIdx.x * blockDim.x + threadIdx.x;

    if (spec) {
        if (i >= B) return;
        const float2* p = (const float2*)theta + (size_t)i * 3;
        float2*       q = (float2*)out        + (size_t)i * 3;
        const size_t  step = (size_t)stride * 3;

        float2 v0 = p[0], v1 = p[1], v2 = p[2];
        while (true) {
            bool more = (i + stride < B);
            const float2* pn = p + step;
            float2 n0, n1, n2;
            if (more) { n0 = pn[0]; n1 = pn[1]; n2 = pn[2]; }  // prefetch

            float o[6];
            fk_spec(v0, v1, v2, o);
            q[0] = make_float2(o[0], o[1]);
            q[1] = make_float2(o[2], o[3]);
            q[2] = make_float2(o[4], o[5]);

            if (!more) break;
            i += stride; p = pn; q += step;
            v0 = n0; v1 = n1; v2 = n2;
        }
        return;
    }

    // ---------------- Generic fallback (cold path) ----------------
    int tx = threadIdx.x;
    if (tx < 6) {
        float al = dh[tx * 4 + 1] * DEG2RAD;
        float sa, ca;
        sincosf(al, &sa, &ca);
        s_ca[tx]  = ca;
        s_sa[tx]  = sa;
        s_a[tx]   = dh[tx * 4 + 0];
        s_d[tx]   = dh[tx * 4 + 2];
        s_off[tx] = dh[tx * 4 + 3] * DEG2RAD;
    }
    __syncthreads();

    for (; i < B; i += stride) {
        const float2* p = (const float2*)theta + (size_t)i * 3;
        float2 v0 = p[0], v1 = p[1], v2 = p[2];
        float o[6];
        fk_generic(v0, v1, v2, o, s_ca, s_sa, s_a, s_d, s_off);
        float2* q = (float2*)out + (size_t)i * 3;
        q[0] = make_float2(o[0], o[1]);
        q[1] = make_float2(o[2], o[3]);
        q[2] = make_float2(o[4], o[5]);
    }
}

extern "C" void kernel_launch(void* const* d_in, const int* in_sizes, int n_in,
                              void* d_out, int out_size) {
    const float* theta = (const float*)d_in[0];
    const float* dh    = (const float*)d_in[1];
    float* out         = (float*)d_out;
    int B = in_sizes[0] / 6;
    int block = 256;
    int grid_needed = (B + block - 1) / block;
    int grid = grid_needed < 1024 ? grid_needed : 1024;   // persistent-ish
    fk_kernel<<<grid, block>>>(theta, dh, out, B);
}

// round 15
// speedup vs baseline: 1.1805x; 1.1805x over previous
#include <cuda_runtime.h>
#include <math.h>

#define DEG2RAD 0.017453292519943295f
#define RAD2DEG 57.29577951308232f
#define TINY    1e-6f

// Expected DH table (all entries exactly-representable in fp32)
__constant__ float c_E[24] = {0.f,180.f,-650.f,0.f,  270.f,90.f,0.f,0.f,
                              800.f,0.f,0.f,0.f,     140.f,90.f,-908.f,0.f,
                              0.f,-96.f,0.f,0.f,     0.f,-65.f,260.f,0.f};

__device__ __forceinline__ void fsincos(float ang, float& s, float& c) {
    s = __sinf(ang);
    c = __cosf(ang);
}

__device__ __forceinline__ float sqrt_approx(float x) {
    float r;
    asm("sqrt.approx.f32 %0, %1;" : "=f"(r) : "f"(x));
    return r;
}

// Fast atan2 (radians), max abs err ~1e-5 rad. Small (<1) polynomial
// coefficients — immediate-friendly on sm_103a.
__device__ __forceinline__ float fast_atan2(float y, float x) {
    float ax = fabsf(x), ay = fabsf(y);
    float mx = fmaxf(ax, ay), mn = fminf(ax, ay);
    float t  = __fdividef(mn, mx);
    float t2 = t * t;
    float p;
    p = fmaf(t2, -0.01172120f, 0.05265332f);
    p = fmaf(t2, p, -0.11643287f);
    p = fmaf(t2, p,  0.19354346f);
    p = fmaf(t2, p, -0.33262347f);
    p = fmaf(t2, p,  0.99997726f);
    float r = p * t;
    if (ay > ax)  r = 1.5707963705f - r;
    if (x < 0.0f) r = 3.1415927410f - r;
    return copysignf(r, y);
}

// x guaranteed >= 0: skips the x<0 quadrant fixup
__device__ __forceinline__ float fast_atan2_posx(float y, float x) {
    float ay = fabsf(y);
    float mx = fmaxf(x, ay), mn = fminf(x, ay);
    float t  = __fdividef(mn, mx);
    float t2 = t * t;
    float p;
    p = fmaf(t2, -0.01172120f, 0.05265332f);
    p = fmaf(t2, p, -0.11643287f);
    p = fmaf(t2, p,  0.19354346f);
    p = fmaf(t2, p, -0.33262347f);
    p = fmaf(t2, p,  0.99997726f);
    float r = p * t;
    if (ay > x) r = 1.5707963705f - r;
    return copysignf(r, y);
}

// Specialized FK for the known DH table (dead T20 trimmed, lazy row-1 joint 5).
__device__ __forceinline__ void fk_spec(float2 v0, float2 v1, float2 v2, float o[6]) {
    float a0 = v0.x * DEG2RAD, a1 = v0.y * DEG2RAD;
    float a2 = v1.x * DEG2RAD, a3 = v1.y * DEG2RAD;
    float a4 = v2.x * DEG2RAD, a5 = v2.y * DEG2RAD;

    float s0, c0, s1, c1, s12, c12, s3, c3, s4, c4, s5, c5;
    fsincos(a0, s0, c0);
    fsincos(a1, s1, c1);
    fsincos(a1 + a2, s12, c12);
    fsincos(a3, s3, c3);
    fsincos(a4, s4, c4);
    fsincos(a5, s5, c5);

    // Closed form of T = T0*T1*T2*T3 (alphas 180,90,0,90; offsets 0):
    float P = fmaf(140.f, c12, fmaf(-908.f, s12, fmaf(800.f, c1, 270.f)));
    float Q = fmaf(-800.f, s1, fmaf(-140.f, s12, fmaf(-908.f, c12, 650.f)));
    float c0c12 = c0 * c12, s0c12 = s0 * c12;

    float T00 = fmaf(c3, c0c12, s3 * s0);
    float T01 = fmaf(-s3, c0c12, c3 * s0);
    float T02 = c0 * s12;
    float T03 = c0 * P;
    float T10 = fmaf(-c3, s0c12, s3 * c0);
    float T11 = fmaf(s3, s0c12, c3 * c0);
    float T12 = -s0 * s12;
    float T13 = -s0 * P;
    float T20 = -c3 * s12;
    float T21 = s3 * s12;
    float T22 = c12;
    float T23 = Q;

    // Joint 4: alpha=-96deg, a=0, d=0 (translation unchanged)
    const float ca4 = -0.10452846326765347f, sa4 = -0.9945218953682733f;
    {
        float u, v, n0, n1;
        u = fmaf(ca4, T01, sa4 * T02); v = fmaf(ca4, T02, -sa4 * T01);
        n0 = fmaf(c4, T00, s4 * u); n1 = fmaf(-s4, T00, c4 * u);
        T00 = n0; T01 = n1; T02 = v;
        u = fmaf(ca4, T11, sa4 * T12); v = fmaf(ca4, T12, -sa4 * T11);
        n0 = fmaf(c4, T10, s4 * u); n1 = fmaf(-s4, T10, c4 * u);
        T10 = n0; T11 = n1; T12 = v;
        // row 2: T20 after this joint is never consumed downstream
        u = fmaf(ca4, T21, sa4 * T22); v = fmaf(ca4, T22, -sa4 * T21);
        n1 = fmaf(-s4, T20, c4 * u);
        T21 = n1; T22 = v;
    }

    // Joint 5: alpha=-65deg, a=0, d=260
    const float ca5 = 0.42261826174069944f, sa5 = -0.9063077870366499f;
    float T00f, T01f, T02f, T12f, T22f;
    {
        float u = fmaf(ca5, T01, sa5 * T02);
        T02f = fmaf(ca5, T02, -sa5 * T01);
        T00f = fmaf(c5, T00, s5 * u);
        T01f = fmaf(-s5, T00, c5 * u);
        T03  = fmaf(260.f, T02f, T03);
        // row 1: final T10/T11 only needed in the rare gimbal branch
        T12f = fmaf(ca5, T12, -sa5 * T11);
        T13  = fmaf(260.f, T12f, T13);
        // row 2: only T22, T23 needed downstream
        T22f = fmaf(ca5, T22, -sa5 * T21);
        T23  = fmaf(260.f, T22f, T23);
    }

    // Euler extraction (common path; identity cosA*T00 - sinA*T01 = sqrt(r2))
    float r2 = fmaf(T00f, T00f, T01f * T01f);
    float A  = fast_atan2(-T01f, T00f) * RAD2DEG;
    float Bd = fast_atan2_posx(T02f, sqrt_approx(r2)) * RAD2DEG;
    float C  = fast_atan2(-T12f, T22f) * RAD2DEG;

    bool cond = (fabsf(T12f) <= TINY) && (fabsf(T22f) <= TINY);
    if (cond) {   // rare gimbal branch: lazily finish row 1 of joint 5
        float u1   = fmaf(ca5, T11, sa5 * T12);
        float T10f = fmaf(c5, T10, s5 * u1);
        float T11f = fmaf(-s5, T10, c5 * u1);
        A  = fast_atan2(T10f, T11f) * RAD2DEG;
        Bd = fast_atan2(T02f, T22f) * RAD2DEG;
        C  = 0.f;
    }

    o[0] = T03; o[1] = T13; o[2] = T23; o[3] = A; o[4] = Bd; o[5] = C;
}

// Generic fallback using runtime DH parameters (shared mem). Cold path.
__device__ void fk_generic(float2 v0, float2 v1, float2 v2, float o[6],
                           const float* ca_, const float* sa_,
                           const float* a_, const float* d_,
                           const float* off_) {
    float th[6] = {v0.x, v0.y, v1.x, v1.y, v2.x, v2.y};
    float T[3][4];
    {
        float s, c;
        fsincos(fmaf(th[0], DEG2RAD, off_[0]), s, c);
        float ca = ca_[0], sa = sa_[0], a = a_[0], d = d_[0];
        T[0][0] = c;      T[0][1] = -s;     T[0][2] = 0.f;  T[0][3] = a;
        T[1][0] = s * ca; T[1][1] = c * ca; T[1][2] = -sa;  T[1][3] = -sa * d;
        T[2][0] = s * sa; T[2][1] = c * sa; T[2][2] = ca;   T[2][3] = ca * d;
    }
    #pragma unroll
    for (int j = 1; j < 6; j++) {
        float s, c;
        fsincos(fmaf(th[j], DEG2RAD, off_[j]), s, c);
        float ca = ca_[j], sa = sa_[j], a = a_[j], d = d_[j];
        #pragma unroll
        for (int r = 0; r < 3; r++) {
            float t0 = T[r][0], t1 = T[r][1], t2 = T[r][2], t3 = T[r][3];
            float u = fmaf(ca, t1, sa * t2);
            float v = fmaf(ca, t2, -sa * t1);
            if (!(j == 5 && r == 2)) {
                T[r][0] = fmaf(c, t0,  s * u);
                T[r][1] = fmaf(-s, t0, c * u);
            }
            T[r][2] = v;
            T[r][3] = fmaf(a, t0, fmaf(d, v, t3));
        }
    }
    float T00 = T[0][0], T01 = T[0][1], T02 = T[0][2];
    float T10 = T[1][0], T11 = T[1][1], T12 = T[1][2];
    float T22 = T[2][2];

    float r2 = fmaf(T00, T00, T01 * T01);
    float A  = fast_atan2(-T01, T00) * RAD2DEG;
    float Bd = fast_atan2_posx(T02, sqrt_approx(r2)) * RAD2DEG;
    float C  = fast_atan2(-T12, T22) * RAD2DEG;

    bool cond = (fabsf(T12) <= TINY) && (fabsf(T22) <= TINY);
    if (cond) {
        A  = fast_atan2(T10, T11) * RAD2DEG;
        Bd = fast_atan2(T02, T22) * RAD2DEG;
        C  = 0.f;
    }
    o[0] = T[0][3]; o[1] = T[1][3]; o[2] = T[2][3]; o[3] = A; o[4] = Bd; o[5] = C;
}

// Single persistent kernel. Warp-level DH check (no barrier, no extra launch);
// grid-stride loop with software prefetch; pointer-increment addressing.
__global__ __launch_bounds__(256)
void fk_kernel(const float* __restrict__ theta,
               const float* __restrict__ dh,
               float* __restrict__ out, int B) {
    __shared__ float s_a[6], s_d[6], s_ca[6], s_sa[6], s_off[6];

    // Warp-uniform DH check: lanes 0-23 compare one element each (one
    // coalesced LDG, L1-hot after the first warp), then ballot.
    int lane = threadIdx.x & 31;
    bool okl = (lane < 24) ? (dh[lane] == c_E[lane]) : true;
    const bool spec = __all_sync(0xffffffffu, okl);

    int stride = gridDim.x * blockDim.x;
    int i = blockIdx.x * blockDim.x + threadIdx.x;

    if (spec) {
        if (i >= B) return;
        const float2* p = (const float2*)theta + (size_t)i * 3;
        float2*       q = (float2*)out        + (size_t)i * 3;
        const size_t  step = (size_t)stride * 3;

        float2 v0 = p[0], v1 = p[1], v2 = p[2];
        while (true) {
            bool more = (i + stride < B);
            const float2* pn = p + step;
            float2 n0, n1, n2;
            if (more) { n0 = pn[0]; n1 = pn[1]; n2 = pn[2]; }  // prefetch

            float o[6];
            fk_spec(v0, v1, v2, o);
            q[0] = make_float2(o[0], o[1]);
            q[1] = make_float2(o[2], o[3]);
            q[2] = make_float2(o[4], o[5]);

            if (!more) break;
            i += stride; p = pn; q += step;
            v0 = n0; v1 = n1; v2 = n2;
        }
        return;
    }

    // ---------------- Generic fallback (cold path) ----------------
    int tx = threadIdx.x;
    if (tx < 6) {
        float al = dh[tx * 4 + 1] * DEG2RAD;
        float sa, ca;
        sincosf(al, &sa, &ca);
        s_ca[tx]  = ca;
        s_sa[tx]  = sa;
        s_a[tx]   = dh[tx * 4 + 0];
        s_d[tx]   = dh[tx * 4 + 2];
        s_off[tx] = dh[tx * 4 + 3] * DEG2RAD;
    }
    __syncthreads();

    for (; i < B; i += stride) {
        const float2* p = (const float2*)theta + (size_t)i * 3;
        float2 v0 = p[0], v1 = p[1], v2 = p[2];
        float o[6];
        fk_generic(v0, v1, v2, o, s_ca, s_sa, s_a, s_d, s_off);
        float2* q = (float2*)out + (size_t)i * 3;
        q[0] = make_float2(o[0], o[1]);
        q[1] = make_float2(o[2], o[3]);
        q[2] = make_float2(o[4], o[5]);
    }
}

extern "C" void kernel_launch(void* const* d_in, const int* in_sizes, int n_in,
                              void* d_out, int out_size) {
    const float* theta = (const float*)d_in[0];
    const float* dh    = (const float*)d_in[1];
    float* out         = (float*)d_out;
    int B = in_sizes[0] / 6;
    int block = 256;
    int grid_needed = (B + block - 1) / block;
    int grid = grid_needed < 1024 ? grid_needed : 1024;   // persistent-ish
    fk_kernel<<<grid, block>>>(theta, dh, out, B);
}

// round 16
// speedup vs baseline: 1.1834x; 1.0025x over previous
#include <cuda_runtime.h>
#include <math.h>

#define DEG2RAD 0.017453292519943295f
#define RAD2DEG 57.29577951308232f
#define TINY    1e-6f

// Expected DH table (all entries exactly-representable in fp32)
__constant__ float c_E[24] = {0.f,180.f,-650.f,0.f,  270.f,90.f,0.f,0.f,
                              800.f,0.f,0.f,0.f,     140.f,90.f,-908.f,0.f,
                              0.f,-96.f,0.f,0.f,     0.f,-65.f,260.f,0.f};

__device__ __forceinline__ void fsincos(float ang, float& s, float& c) {
    s = __sinf(ang);
    c = __cosf(ang);
}

__device__ __forceinline__ float sqrt_approx(float x) {
    float r;
    asm("sqrt.approx.f32 %0, %1;" : "=f"(r) : "f"(x));
    return r;
}

// Fast atan2 (radians), max abs err ~1e-5 rad. Small (<1) polynomial
// coefficients — immediate-friendly on sm_103a.
__device__ __forceinline__ float fast_atan2(float y, float x) {
    float ax = fabsf(x), ay = fabsf(y);
    float mx = fmaxf(ax, ay), mn = fminf(ax, ay);
    float t  = __fdividef(mn, mx);
    float t2 = t * t;
    float p;
    p = fmaf(t2, -0.01172120f, 0.05265332f);
    p = fmaf(t2, p, -0.11643287f);
    p = fmaf(t2, p,  0.19354346f);
    p = fmaf(t2, p, -0.33262347f);
    p = fmaf(t2, p,  0.99997726f);
    float r = p * t;
    if (ay > ax)  r = 1.5707963705f - r;
    if (x < 0.0f) r = 3.1415927410f - r;
    return copysignf(r, y);
}

// x guaranteed >= 0: skips the x<0 quadrant fixup
__device__ __forceinline__ float fast_atan2_posx(float y, float x) {
    float ay = fabsf(y);
    float mx = fmaxf(x, ay), mn = fminf(x, ay);
    float t  = __fdividef(mn, mx);
    float t2 = t * t;
    float p;
    p = fmaf(t2, -0.01172120f, 0.05265332f);
    p = fmaf(t2, p, -0.11643287f);
    p = fmaf(t2, p,  0.19354346f);
    p = fmaf(t2, p, -0.33262347f);
    p = fmaf(t2, p,  0.99997726f);
    float r = p * t;
    if (ay > x) r = 1.5707963705f - r;
    return copysignf(r, y);
}

// Specialized FK for the known DH table (dead T20 trimmed, lazy row-1 joint 5).
__device__ __forceinline__ void fk_spec(float2 v0, float2 v1, float2 v2, float o[6]) {
    float a0 = v0.x * DEG2RAD, a1 = v0.y * DEG2RAD;
    float a2 = v1.x * DEG2RAD, a3 = v1.y * DEG2RAD;
    float a4 = v2.x * DEG2RAD, a5 = v2.y * DEG2RAD;

    float s0, c0, s1, c1, s12, c12, s3, c3, s4, c4, s5, c5;
    fsincos(a0, s0, c0);
    fsincos(a1, s1, c1);
    fsincos(a1 + a2, s12, c12);
    fsincos(a3, s3, c3);
    fsincos(a4, s4, c4);
    fsincos(a5, s5, c5);

    // Closed form of T = T0*T1*T2*T3 (alphas 180,90,0,90; offsets 0):
    float P = fmaf(140.f, c12, fmaf(-908.f, s12, fmaf(800.f, c1, 270.f)));
    float Q = fmaf(-800.f, s1, fmaf(-140.f, s12, fmaf(-908.f, c12, 650.f)));
    float c0c12 = c0 * c12, s0c12 = s0 * c12;

    float T00 = fmaf(c3, c0c12, s3 * s0);
    float T01 = fmaf(-s3, c0c12, c3 * s0);
    float T02 = c0 * s12;
    float T03 = c0 * P;
    float T10 = fmaf(-c3, s0c12, s3 * c0);
    float T11 = fmaf(s3, s0c12, c3 * c0);
    float T12 = -s0 * s12;
    float T13 = -s0 * P;
    float T20 = -c3 * s12;
    float T21 = s3 * s12;
    float T22 = c12;
    float T23 = Q;

    // Joint 4: alpha=-96deg, a=0, d=0 (translation unchanged)
    const float ca4 = -0.10452846326765347f, sa4 = -0.9945218953682733f;
    {
        float u, v, n0, n1;
        u = fmaf(ca4, T01, sa4 * T02); v = fmaf(ca4, T02, -sa4 * T01);
        n0 = fmaf(c4, T00, s4 * u); n1 = fmaf(-s4, T00, c4 * u);
        T00 = n0; T01 = n1; T02 = v;
        u = fmaf(ca4, T11, sa4 * T12); v = fmaf(ca4, T12, -sa4 * T11);
        n0 = fmaf(c4, T10, s4 * u); n1 = fmaf(-s4, T10, c4 * u);
        T10 = n0; T11 = n1; T12 = v;
        // row 2: T20 after this joint is never consumed downstream
        u = fmaf(ca4, T21, sa4 * T22); v = fmaf(ca4, T22, -sa4 * T21);
        n1 = fmaf(-s4, T20, c4 * u);
        T21 = n1; T22 = v;
    }

    // Joint 5: alpha=-65deg, a=0, d=260
    const float ca5 = 0.42261826174069944f, sa5 = -0.9063077870366499f;
    float T00f, T01f, T02f, T12f, T22f;
    {
        float u = fmaf(ca5, T01, sa5 * T02);
        T02f = fmaf(ca5, T02, -sa5 * T01);
        T00f = fmaf(c5, T00, s5 * u);
        T01f = fmaf(-s5, T00, c5 * u);
        T03  = fmaf(260.f, T02f, T03);
        // row 1: final T10/T11 only needed in the rare gimbal branch
        T12f = fmaf(ca5, T12, -sa5 * T11);
        T13  = fmaf(260.f, T12f, T13);
        // row 2: only T22, T23 needed downstream
        T22f = fmaf(ca5, T22, -sa5 * T21);
        T23  = fmaf(260.f, T22f, T23);
    }

    // Euler extraction (common path; identity cosA*T00 - sinA*T01 = sqrt(r2))
    float r2 = fmaf(T00f, T00f, T01f * T01f);
    float A  = fast_atan2(-T01f, T00f) * RAD2DEG;
    float Bd = fast_atan2_posx(T02f, sqrt_approx(r2)) * RAD2DEG;
    float C  = fast_atan2(-T12f, T22f) * RAD2DEG;

    bool cond = (fabsf(T12f) <= TINY) && (fabsf(T22f) <= TINY);
    if (cond) {   // rare gimbal branch: lazily finish row 1 of joint 5
        float u1   = fmaf(ca5, T11, sa5 * T12);
        float T10f = fmaf(c5, T10, s5 * u1);
        float T11f = fmaf(-s5, T10, c5 * u1);
        A  = fast_atan2(T10f, T11f) * RAD2DEG;
        Bd = fast_atan2(T02f, T22f) * RAD2DEG;
        C  = 0.f;
    }

    o[0] = T03; o[1] = T13; o[2] = T23; o[3] = A; o[4] = Bd; o[5] = C;
}

// Generic fallback using runtime DH parameters (shared mem). Cold path.
__device__ void fk_generic(float2 v0, float2 v1, float2 v2, float o[6],
                           const float* ca_, const float* sa_,
                           const float* a_, const float* d_,
                           const float* off_) {
    float th[6] = {v0.x, v0.y, v1.x, v1.y, v2.x, v2.y};
    float T[3][4];
    {
        float s, c;
        fsincos(fmaf(th[0], DEG2RAD, off_[0]), s, c);
        float ca = ca_[0], sa = sa_[0], a = a_[0], d = d_[0];
        T[0][0] = c;      T[0][1] = -s;     T[0][2] = 0.f;  T[0][3] = a;
        T[1][0] = s * ca; T[1][1] = c * ca; T[1][2] = -sa;  T[1][3] = -sa * d;
        T[2][0] = s * sa; T[2][1] = c * sa; T[2][2] = ca;   T[2][3] = ca * d;
    }
    #pragma unroll
    for (int j = 1; j < 6; j++) {
        float s, c;
        fsincos(fmaf(th[j], DEG2RAD, off_[j]), s, c);
        float ca = ca_[j], sa = sa_[j], a = a_[j], d = d_[j];
        #pragma unroll
        for (int r = 0; r < 3; r++) {
            float t0 = T[r][0], t1 = T[r][1], t2 = T[r][2], t3 = T[r][3];
            float u = fmaf(ca, t1, sa * t2);
            float v = fmaf(ca, t2, -sa * t1);
            if (!(j == 5 && r == 2)) {
                T[r][0] = fmaf(c, t0,  s * u);
                T[r][1] = fmaf(-s, t0, c * u);
            }
            T[r][2] = v;
            T[r][3] = fmaf(a, t0, fmaf(d, v, t3));
        }
    }
    float T00 = T[0][0], T01 = T[0][1], T02 = T[0][2];
    float T10 = T[1][0], T11 = T[1][1], T12 = T[1][2];
    float T22 = T[2][2];

    float r2 = fmaf(T00, T00, T01 * T01);
    float A  = fast_atan2(-T01, T00) * RAD2DEG;
    float Bd = fast_atan2_posx(T02, sqrt_approx(r2)) * RAD2DEG;
    float C  = fast_atan2(-T12, T22) * RAD2DEG;

    bool cond = (fabsf(T12) <= TINY) && (fabsf(T22) <= TINY);
    if (cond) {
        A  = fast_atan2(T10, T11) * RAD2DEG;
        Bd = fast_atan2(T02, T22) * RAD2DEG;
        C  = 0.f;
    }
    o[0] = T[0][3]; o[1] = T[1][3]; o[2] = T[2][3]; o[3] = A; o[4] = Bd; o[5] = C;
}

// Single persistent kernel, exactly ONE wave (148 SMs x 4 blocks @ 63 regs).
// Warp-level DH check (no barrier, no extra launch); grid-stride loop with
// software prefetch; pointer-increment addressing.
__global__ __launch_bounds__(256)
void fk_kernel(const float* __restrict__ theta,
               const float* __restrict__ dh,
               float* __restrict__ out, int B) {
    __shared__ float s_a[6], s_d[6], s_ca[6], s_sa[6], s_off[6];

    // Warp-uniform DH check: lanes 0-23 compare one element each (one
    // coalesced LDG, L1-hot after the first warp), then ballot.
    int lane = threadIdx.x & 31;
    bool okl = (lane < 24) ? (dh[lane] == c_E[lane]) : true;
    const bool spec = __all_sync(0xffffffffu, okl);

    int stride = gridDim.x * blockDim.x;
    int i = blockIdx.x * blockDim.x + threadIdx.x;

    if (spec) {
        if (i >= B) return;
        const float2* p = (const float2*)theta + (size_t)i * 3;
        float2*       q = (float2*)out        + (size_t)i * 3;
        const size_t  step = (size_t)stride * 3;

        float2 v0 = p[0], v1 = p[1], v2 = p[2];
        while (true) {
            bool more = (i + stride < B);
            const float2* pn = p + step;
            float2 n0, n1, n2;
            if (more) { n0 = pn[0]; n1 = pn[1]; n2 = pn[2]; }  // prefetch

            float o[6];
            fk_spec(v0, v1, v2, o);
            q[0] = make_float2(o[0], o[1]);
            q[1] = make_float2(o[2], o[3]);
            q[2] = make_float2(o[4], o[5]);

            if (!more) break;
            i += stride; p = pn; q += step;
            v0 = n0; v1 = n1; v2 = n2;
        }
        return;
    }

    // ---------------- Generic fallback (cold path) ----------------
    int tx = threadIdx.x;
    if (tx < 6) {
        float al = dh[tx * 4 + 1] * DEG2RAD;
        float sa, ca;
        sincosf(al, &sa, &ca);
        s_ca[tx]  = ca;
        s_sa[tx]  = sa;
        s_a[tx]   = dh[tx * 4 + 0];
        s_d[tx]   = dh[tx * 4 + 2];
        s_off[tx] = dh[tx * 4 + 3] * DEG2RAD;
    }
    __syncthreads();

    for (; i < B; i += stride) {
        const float2* p = (const float2*)theta + (size_t)i * 3;
        float2 v0 = p[0], v1 = p[1], v2 = p[2];
        float o[6];
        fk_generic(v0, v1, v2, o, s_ca, s_sa, s_a, s_d, s_off);
        float2* q = (float2*)out + (size_t)i * 3;
        q[0] = make_float2(o[0], o[1]);
        q[1] = make_float2(o[2], o[3]);
        q[2] = make_float2(o[4], o[5]);
    }
}

extern "C" void kernel_launch(void* const* d_in, const int* in_sizes, int n_in,
                              void* d_out, int out_size) {
    const float* theta = (const float*)d_in[0];
    const float* dh    = (const float*)d_in[1];
    float* out         = (float*)d_out;
    int B = in_sizes[0] / 6;
    int block = 256;
    int grid_needed = (B + block - 1) / block;
    // Exactly one wave: 148 SMs x 4 resident blocks (63 regs, 256 thr).
    int grid = grid_needed < 592 ? grid_needed : 592;
    fk_kernel<<<grid, block>>>(theta, dh, out, B);
}